// round 2
// baseline (speedup 1.0000x reference)
#include <cuda_runtime.h>
#include <cstdint>
#include <math.h>

// Problem constants
#define BB 32
#define NN 1024
#define DD 1152
#define RR 4
#define MM 256   // NN/RR

// GEMM tile config
#define BM 128
#define BN 128
#define BK 32
#define KST 36   // padded smem row stride (floats): 36*4=144B (16B-aligned), conflict-free

// ---------------- scratch (device globals; no allocation allowed) ----------------
__device__ float g_xr [(size_t)BB * NN * DD];   // rounded x           [32,1024,1152]
__device__ float g_Wr [4][(size_t)DD * DD];     // rounded Wq,Wk,Wv,Wo
__device__ float g_xm [(size_t)BB * MM * DD];   // merged x (rounded)  [32,256,1152]
__device__ float g_Q  [(size_t)BB * NN * DD];   // Q (rounded)         [32,1024,1152]
__device__ float g_Km [(size_t)BB * MM * DD];   // K merged (rounded)  [32,256,1152]
__device__ float g_VmT[(size_t)BB * DD * MM];   // V merged T (rounded)[32,1152,256]
__device__ float g_S  [(size_t)BB * NN * MM];   // scores/probs        [32,1024,256]
__device__ float g_AO [(size_t)BB * NN * DD];   // attn out (rounded)  [32,1024,1152]

// ---------------- helpers ----------------
__device__ __forceinline__ float rtf(float f) {   // round-to-nearest tf32, as float
    uint32_t u;
    asm("cvt.rna.tf32.f32 %0, %1;" : "=r"(u) : "f"(f));
    return __uint_as_float(u);
}

__device__ __forceinline__ void cp_async16(uint32_t smem, const float* gmem) {
    asm volatile("cp.async.cg.shared.global [%0], [%1], 16;\n" :: "r"(smem), "l"(gmem));
}
__device__ __forceinline__ void cp_commit() {
    asm volatile("cp.async.commit_group;\n" ::: "memory");
}

__device__ __forceinline__ void mma_tf32(float c[4], const uint32_t a[4], const uint32_t b[2]) {
    asm volatile(
        "mma.sync.aligned.m16n8k8.row.col.f32.tf32.tf32.f32 "
        "{%0,%1,%2,%3}, {%4,%5,%6,%7}, {%8,%9}, {%0,%1,%2,%3};"
        : "+f"(c[0]), "+f"(c[1]), "+f"(c[2]), "+f"(c[3])
        : "r"(a[0]), "r"(a[1]), "r"(a[2]), "r"(a[3]), "r"(b[0]), "r"(b[1]));
}

// ---------------- kernel 0: elementwise tf32-round (vectorized) ----------------
__global__ __launch_bounds__(256) void round_pass(const float4* __restrict__ in,
                                                  float4* __restrict__ out, int n4) {
    int i = blockIdx.x * 256 + threadIdx.x;
    if (i >= n4) return;
    float4 v = in[i];
    v.x = rtf(v.x); v.y = rtf(v.y); v.z = rtf(v.z); v.w = rtf(v.w);
    out[i] = v;
}

// ---------------- kernel 1: window-mean merge  xr[B,N,D] -> xm[B,M,D] (rounded) ----------------
__global__ __launch_bounds__(256) void merge_mean(const float* __restrict__ x,
                                                  float* __restrict__ xm) {
    const int D4 = DD / 4;  // 288
    size_t idx = (size_t)blockIdx.x * blockDim.x + threadIdx.x;
    size_t tot = (size_t)BB * MM * D4;
    if (idx >= tot) return;
    int d4 = (int)(idx % D4);
    size_t orow = idx / D4;           // b*256 + m
    int b = (int)(orow >> 8);
    int m = (int)(orow & 255);
    const float4* base = (const float4*)x + ((size_t)b * NN + (size_t)m * RR) * D4 + d4;
    float4 a0 = base[0];
    float4 a1 = base[D4];
    float4 a2 = base[2 * D4];
    float4 a3 = base[3 * D4];
    float4 o;
    o.x = rtf(0.25f * (a0.x + a1.x + a2.x + a3.x));
    o.y = rtf(0.25f * (a0.y + a1.y + a2.y + a3.y));
    o.z = rtf(0.25f * (a0.z + a1.z + a2.z + a3.z));
    o.w = rtf(0.25f * (a0.w + a1.w + a2.w + a3.w));
    ((float4*)xm)[idx] = o;
}

// ---------------- kernel 2: generic batched tf32 GEMM (operands pre-rounded) ----------------
// C[b][i][j] = alpha * sum_k A[b][i][k] * Bm[b][j][k]  (+ bias[j] if bias)
// If transC: C[b] laid out [Ncols][Mrows]. If roundC: outputs rounded to tf32.
// Requires: Mrows%128==0, Ncols%128==0, K%32==0, 16B-aligned pointers.
__global__ __launch_bounds__(256) void gemm_tf32(
    const float* __restrict__ A, const float* __restrict__ Bm,
    const float* __restrict__ bias, float* __restrict__ C,
    int Mrows, int Ncols, int K,
    long long sA, long long sB, long long sC,
    float alpha, int transC, int roundC)
{
    __shared__ float As[2][BM * KST];
    __shared__ float Bs[2][BN * KST];

    const int bz = blockIdx.z;
    const float* Ab = A + (size_t)bz * sA;
    const float* Bb = Bm + (size_t)bz * sB;
    float* Cb = C + (size_t)bz * sC;

    const int tid = threadIdx.x;
    const int warp = tid >> 5, lane = tid & 31;
    const int wm = warp & 1;        // 0..1 (64 rows each)
    const int wn = warp >> 1;       // 0..3 (32 cols each)
    const int rr = lane >> 2;       // group id 0..7
    const int cc = lane & 3;        // thread-in-group

    const int rowA0 = blockIdx.x * BM;
    const int rowB0 = blockIdx.y * BN;

    float acc[4][4][4];
#pragma unroll
    for (int i = 0; i < 4; i++)
#pragma unroll
        for (int j = 0; j < 4; j++)
#pragma unroll
            for (int k = 0; k < 4; k++) acc[i][j][k] = 0.0f;

    const int KT = K / BK;

    // per-thread load assignment: 128 rows x 32 floats = 1024 16B-chunks per operand
    auto load_tile = [&](int buf, int kt) {
#pragma unroll
        for (int i = 0; i < 4; i++) {
            int c = tid + i * 256;
            int r = c >> 3;
            int kv = (c & 7) * 4;
            const float* gA = Ab + (size_t)(rowA0 + r) * K + kt * BK + kv;
            uint32_t sa = (uint32_t)__cvta_generic_to_shared(&As[buf][r * KST + kv]);
            cp_async16(sa, gA);
            const float* gB = Bb + (size_t)(rowB0 + r) * K + kt * BK + kv;
            uint32_t sb = (uint32_t)__cvta_generic_to_shared(&Bs[buf][r * KST + kv]);
            cp_async16(sb, gB);
        }
        cp_commit();
    };

    load_tile(0, 0);

    for (int kt = 0; kt < KT; kt++) {
        const int buf = kt & 1;
        if (kt + 1 < KT) {
            load_tile(buf ^ 1, kt + 1);
            asm volatile("cp.async.wait_group 1;\n" ::: "memory");
        } else {
            asm volatile("cp.async.wait_group 0;\n" ::: "memory");
        }
        __syncthreads();

        const uint32_t* As_ = (const uint32_t*)&As[buf][0];
        const uint32_t* Bs_ = (const uint32_t*)&Bs[buf][0];
#pragma unroll
        for (int ks = 0; ks < 4; ks++) {
            const int kb = ks * 8;
            uint32_t af[4][4], bf[4][2];
#pragma unroll
            for (int mi = 0; mi < 4; mi++) {
                int base = (wm * 64 + mi * 16 + rr) * KST + kb + cc;
                af[mi][0] = As_[base];
                af[mi][1] = As_[base + 8 * KST];
                af[mi][2] = As_[base + 4];
                af[mi][3] = As_[base + 8 * KST + 4];
            }
#pragma unroll
            for (int ni = 0; ni < 4; ni++) {
                int base = (wn * 32 + ni * 8 + rr) * KST + kb + cc;
                bf[ni][0] = Bs_[base];
                bf[ni][1] = Bs_[base + 4];
            }
#pragma unroll
            for (int mi = 0; mi < 4; mi++)
#pragma unroll
                for (int ni = 0; ni < 4; ni++)
                    mma_tf32(acc[mi][ni], af[mi], bf[ni]);
        }
        __syncthreads();
    }

    // epilogue
#pragma unroll
    for (int mi = 0; mi < 4; mi++) {
#pragma unroll
        for (int ni = 0; ni < 4; ni++) {
            int gr = rowA0 + wm * 64 + mi * 16 + rr;
            int gc = rowB0 + wn * 32 + ni * 8 + 2 * cc;
            float b0v = 0.0f, b1v = 0.0f;
            if (bias) { b0v = bias[gc]; b1v = bias[gc + 1]; }
            float v00 = acc[mi][ni][0] * alpha + b0v;
            float v01 = acc[mi][ni][1] * alpha + b1v;
            float v10 = acc[mi][ni][2] * alpha + b0v;
            float v11 = acc[mi][ni][3] * alpha + b1v;
            if (roundC) {
                v00 = rtf(v00); v01 = rtf(v01); v10 = rtf(v10); v11 = rtf(v11);
            }
            if (!transC) {
                float2* o0 = (float2*)(Cb + (size_t)gr * Ncols + gc);
                *o0 = make_float2(v00, v01);
                float2* o1 = (float2*)(Cb + (size_t)(gr + 8) * Ncols + gc);
                *o1 = make_float2(v10, v11);
            } else {
                Cb[(size_t)gc * Mrows + gr]           = v00;
                Cb[(size_t)(gc + 1) * Mrows + gr]     = v01;
                Cb[(size_t)gc * Mrows + gr + 8]       = v10;
                Cb[(size_t)(gc + 1) * Mrows + gr + 8] = v11;
            }
        }
    }
}

// ---------------- kernel 3: softmax over last dim (256), in place, rounded probs ----------------
__global__ __launch_bounds__(256) void softmax256(float* __restrict__ S) {
    int row = blockIdx.x * 8 + (threadIdx.x >> 5);
    int lane = threadIdx.x & 31;
    float4* p = (float4*)(S + (size_t)row * MM);
    float4 v0 = p[lane];
    float4 v1 = p[lane + 32];

    float m = fmaxf(fmaxf(fmaxf(v0.x, v0.y), fmaxf(v0.z, v0.w)),
                    fmaxf(fmaxf(v1.x, v1.y), fmaxf(v1.z, v1.w)));
#pragma unroll
    for (int off = 16; off > 0; off >>= 1)
        m = fmaxf(m, __shfl_xor_sync(0xFFFFFFFFu, m, off));

    v0.x = __expf(v0.x - m); v0.y = __expf(v0.y - m);
    v0.z = __expf(v0.z - m); v0.w = __expf(v0.w - m);
    v1.x = __expf(v1.x - m); v1.y = __expf(v1.y - m);
    v1.z = __expf(v1.z - m); v1.w = __expf(v1.w - m);

    float s = v0.x + v0.y + v0.z + v0.w + v1.x + v1.y + v1.z + v1.w;
#pragma unroll
    for (int off = 16; off > 0; off >>= 1)
        s += __shfl_xor_sync(0xFFFFFFFFu, s, off);

    float inv = 1.0f / s;
    v0.x = rtf(v0.x * inv); v0.y = rtf(v0.y * inv);
    v0.z = rtf(v0.z * inv); v0.w = rtf(v0.w * inv);
    v1.x = rtf(v1.x * inv); v1.y = rtf(v1.y * inv);
    v1.z = rtf(v1.z * inv); v1.w = rtf(v1.w * inv);
    p[lane] = v0;
    p[lane + 32] = v1;
}

// ---------------- launch ----------------
extern "C" void kernel_launch(void* const* d_in, const int* in_sizes, int n_in,
                              void* d_out, int out_size) {
    static float *p_xr = nullptr, *p_W0, *p_W1, *p_W2, *p_W3,
                 *p_xm, *p_Q, *p_Km, *p_VmT, *p_S, *p_AO;
    if (!p_xr) {
        float* wbase;
        cudaGetSymbolAddress((void**)&p_xr,  g_xr);
        cudaGetSymbolAddress((void**)&wbase, g_Wr);
        p_W0 = wbase;
        p_W1 = wbase + (size_t)DD * DD;
        p_W2 = wbase + 2 * (size_t)DD * DD;
        p_W3 = wbase + 3 * (size_t)DD * DD;
        cudaGetSymbolAddress((void**)&p_xm,  g_xm);
        cudaGetSymbolAddress((void**)&p_Q,   g_Q);
        cudaGetSymbolAddress((void**)&p_Km,  g_Km);
        cudaGetSymbolAddress((void**)&p_VmT, g_VmT);
        cudaGetSymbolAddress((void**)&p_S,   g_S);
        cudaGetSymbolAddress((void**)&p_AO,  g_AO);
    }

    const float* x  = (const float*)d_in[0];
    const float* Wq = (const float*)d_in[1];
    const float* bq = (const float*)d_in[2];
    const float* Wk = (const float*)d_in[3];
    const float* bk = (const float*)d_in[4];
    const float* Wv = (const float*)d_in[5];
    const float* bv = (const float*)d_in[6];
    const float* Wo = (const float*)d_in[7];
    const float* bo = (const float*)d_in[8];
    float* out = (float*)d_out;

    const float scale = 1.0f / sqrtf((float)DD);
    dim3 blk(256);

    // Pre-round inputs to tf32-representable fp32 (removes cvt from GEMM inner loop)
    const int xN4 = BB * NN * (DD / 4);
    const int wN4 = DD * DD / 4;
    round_pass<<<(xN4 + 255) / 256, blk>>>((const float4*)x,  (float4*)p_xr, xN4);
    round_pass<<<(wN4 + 255) / 256, blk>>>((const float4*)Wq, (float4*)p_W0, wN4);
    round_pass<<<(wN4 + 255) / 256, blk>>>((const float4*)Wk, (float4*)p_W1, wN4);
    round_pass<<<(wN4 + 255) / 256, blk>>>((const float4*)Wv, (float4*)p_W2, wN4);
    round_pass<<<(wN4 + 255) / 256, blk>>>((const float4*)Wo, (float4*)p_W3, wN4);

    // 0. x_m = window mean of x_r (rounded)
    merge_mean<<<(BB * MM * (DD / 4)) / 256, blk>>>(p_xr, p_xm);

    // 1. Q = x @ Wq^T + bq      [32768, 1152]  (rounded)
    gemm_tf32<<<dim3((BB * NN) / BM, DD / BN, 1), blk>>>(
        p_xr, p_W0, bq, p_Q, BB * NN, DD, DD, 0, 0, 0, 1.0f, 0, 1);

    // 2. K_m = x_m @ Wk^T + bk  [8192, 1152]  (rounded)
    gemm_tf32<<<dim3((BB * MM) / BM, DD / BN, 1), blk>>>(
        p_xm, p_W1, bk, p_Km, BB * MM, DD, DD, 0, 0, 0, 1.0f, 0, 1);

    // 3. V_mT = (x_m @ Wv^T + bv)^T per batch  -> [32][1152][256]  (rounded)
    gemm_tf32<<<dim3(MM / BM, DD / BN, BB), blk>>>(
        p_xm, p_W2, bv, p_VmT, MM, DD, DD,
        (long long)MM * DD, 0, (long long)DD * MM, 1.0f, 1, 1);

    // 4. S = scale * Q @ K_m^T  (log(npt) bias dropped: softmax-invariant)
    gemm_tf32<<<dim3(NN / BM, MM / BN, BB), blk>>>(
        p_Q, p_Km, nullptr, p_S, NN, MM, DD,
        (long long)NN * DD, (long long)MM * DD, (long long)NN * MM, scale, 0, 0);

    // 5. softmax rows of S (writes rounded probs)
    softmax256<<<(BB * NN) / 8, blk>>>(p_S);

    // 6. AO = P @ V_m   (B operand = V_mT, K-major)  (rounded)
    gemm_tf32<<<dim3(NN / BM, DD / BN, BB), blk>>>(
        p_S, p_VmT, nullptr, p_AO, NN, DD, MM,
        (long long)NN * MM, (long long)DD * MM, (long long)NN * DD, 1.0f, 0, 1);

    // 7. out = AO @ Wo^T + bo   (full fp32 output)
    gemm_tf32<<<dim3((BB * NN) / BM, DD / BN, 1), blk>>>(
        p_AO, p_W3, bo, out, BB * NN, DD, DD, 0, 0, 0, 1.0f, 0, 0);
}

// round 3
// speedup vs baseline: 1.2524x; 1.2524x over previous
#include <cuda_runtime.h>
#include <cstdint>
#include <math.h>

// Problem constants
#define BB 32
#define NN 1024
#define DD 1152
#define RR 4
#define MM 256   // NN/RR

// GEMM tile config (Round-1 proven config)
#define BM 128
#define BN 128
#define BK 16
#define KST 20   // padded smem row stride (floats): 80B, 16B-aligned, conflict-free

// ---------------- scratch (device globals; no allocation allowed) ----------------
__device__ float g_xr [(size_t)BB * NN * DD];   // rounded x           [32,1024,1152]
__device__ float g_Wr [4][(size_t)DD * DD];     // rounded Wq,Wk,Wv,Wo
__device__ float g_xm [(size_t)BB * MM * DD];   // merged x (rounded)  [32,256,1152]
__device__ float g_Q  [(size_t)BB * NN * DD];   // Q (rounded)         [32,1024,1152]
__device__ float g_Km [(size_t)BB * MM * DD];   // K merged (rounded)  [32,256,1152]
__device__ float g_VmT[(size_t)BB * DD * MM];   // V merged T (rounded)[32,1152,256]
__device__ float g_S  [(size_t)BB * NN * MM];   // scores/probs        [32,1024,256]
__device__ float g_AO [(size_t)BB * NN * DD];   // attn out (rounded)  [32,1024,1152]

// ---------------- helpers ----------------
__device__ __forceinline__ float rtf(float f) {   // round-to-nearest tf32, as float
    uint32_t u;
    asm("cvt.rna.tf32.f32 %0, %1;" : "=r"(u) : "f"(f));
    return __uint_as_float(u);
}

__device__ __forceinline__ void cp_async16(uint32_t smem, const float* gmem) {
    asm volatile("cp.async.cg.shared.global [%0], [%1], 16;\n" :: "r"(smem), "l"(gmem));
}
__device__ __forceinline__ void cp_commit() {
    asm volatile("cp.async.commit_group;\n" ::: "memory");
}

__device__ __forceinline__ void mma_tf32(float c[4], const uint32_t a[4], const uint32_t b[2]) {
    asm volatile(
        "mma.sync.aligned.m16n8k8.row.col.f32.tf32.tf32.f32 "
        "{%0,%1,%2,%3}, {%4,%5,%6,%7}, {%8,%9}, {%0,%1,%2,%3};"
        : "+f"(c[0]), "+f"(c[1]), "+f"(c[2]), "+f"(c[3])
        : "r"(a[0]), "r"(a[1]), "r"(a[2]), "r"(a[3]), "r"(b[0]), "r"(b[1]));
}

// ---------------- kernel 0: elementwise tf32-round, 4 float4/thread (MLP=4) ----------------
__global__ __launch_bounds__(256) void round_pass(const float4* __restrict__ in,
                                                  float4* __restrict__ out, int n4) {
    int base = blockIdx.x * 1024 + threadIdx.x;
    float4 v[4];
    int idx[4];
    int cnt = 0;
#pragma unroll
    for (int j = 0; j < 4; j++) {
        int i = base + j * 256;
        if (i < n4) { idx[cnt] = i; v[cnt] = in[i]; cnt++; }
    }
#pragma unroll 4
    for (int j = 0; j < cnt; j++) {
        float4 t = v[j];
        t.x = rtf(t.x); t.y = rtf(t.y); t.z = rtf(t.z); t.w = rtf(t.w);
        out[idx[j]] = t;
    }
}

// ---------------- kernel 1: window-mean merge  xr[B,N,D] -> xm[B,M,D] (rounded) ----------------
__global__ __launch_bounds__(256) void merge_mean(const float* __restrict__ x,
                                                  float* __restrict__ xm) {
    const int D4 = DD / 4;  // 288
    size_t idx = (size_t)blockIdx.x * blockDim.x + threadIdx.x;
    size_t tot = (size_t)BB * MM * D4;
    if (idx >= tot) return;
    int d4 = (int)(idx % D4);
    size_t orow = idx / D4;           // b*256 + m
    int b = (int)(orow >> 8);
    int m = (int)(orow & 255);
    const float4* base = (const float4*)x + ((size_t)b * NN + (size_t)m * RR) * D4 + d4;
    float4 a0 = base[0];
    float4 a1 = base[D4];
    float4 a2 = base[2 * D4];
    float4 a3 = base[3 * D4];
    float4 o;
    o.x = rtf(0.25f * (a0.x + a1.x + a2.x + a3.x));
    o.y = rtf(0.25f * (a0.y + a1.y + a2.y + a3.y));
    o.z = rtf(0.25f * (a0.z + a1.z + a2.z + a3.z));
    o.w = rtf(0.25f * (a0.w + a1.w + a2.w + a3.w));
    ((float4*)xm)[idx] = o;
}

// ---------------- kernel 2: batched tf32 GEMM, operands pre-rounded (no inner CVT) ----------------
// C[b][i][j] = alpha * sum_k A[b][i][k] * Bm[b][j][k]  (+ bias[j] if bias)
// If transC: C[b] laid out [Ncols][Mrows]. If roundC: outputs rounded to tf32.
// Requires: Mrows%128==0, Ncols%128==0, K%16==0, 16B-aligned pointers.
__global__ __launch_bounds__(256) void gemm_tf32(
    const float* __restrict__ A, const float* __restrict__ Bm,
    const float* __restrict__ bias, float* __restrict__ C,
    int Mrows, int Ncols, int K,
    long long sA, long long sB, long long sC,
    float alpha, int transC, int roundC)
{
    __shared__ float As[2][BM * KST];
    __shared__ float Bs[2][BN * KST];

    const int bz = blockIdx.z;
    const float* Ab = A + (size_t)bz * sA;
    const float* Bb = Bm + (size_t)bz * sB;
    float* Cb = C + (size_t)bz * sC;

    const int tid = threadIdx.x;
    const int warp = tid >> 5, lane = tid & 31;
    const int wm = warp & 1;        // 0..1 (64 rows each)
    const int wn = warp >> 1;       // 0..3 (32 cols each)
    const int rr = lane >> 2;       // group id 0..7
    const int cc = lane & 3;        // thread-in-group

    const int rowA0 = blockIdx.x * BM;
    const int rowB0 = blockIdx.y * BN;

    float acc[4][4][4];
#pragma unroll
    for (int i = 0; i < 4; i++)
#pragma unroll
        for (int j = 0; j < 4; j++)
#pragma unroll
            for (int k = 0; k < 4; k++) acc[i][j][k] = 0.0f;

    const int KT = K / BK;

    // per-thread load assignment (512 16B-chunks per operand tile, 256 threads -> 2 each)
    auto load_tile = [&](int buf, int kt) {
#pragma unroll
        for (int i = 0; i < 2; i++) {
            int c = tid + i * 256;
            int r = c >> 2;
            int kv = (c & 3) * 4;
            const float* gA = Ab + (size_t)(rowA0 + r) * K + kt * BK + kv;
            uint32_t sa = (uint32_t)__cvta_generic_to_shared(&As[buf][r * KST + kv]);
            cp_async16(sa, gA);
            const float* gB = Bb + (size_t)(rowB0 + r) * K + kt * BK + kv;
            uint32_t sb = (uint32_t)__cvta_generic_to_shared(&Bs[buf][r * KST + kv]);
            cp_async16(sb, gB);
        }
        cp_commit();
    };

    load_tile(0, 0);

    for (int kt = 0; kt < KT; kt++) {
        const int buf = kt & 1;
        if (kt + 1 < KT) {
            load_tile(buf ^ 1, kt + 1);
            asm volatile("cp.async.wait_group 1;\n" ::: "memory");
        } else {
            asm volatile("cp.async.wait_group 0;\n" ::: "memory");
        }
        __syncthreads();

        const uint32_t* As_ = (const uint32_t*)&As[buf][0];
        const uint32_t* Bs_ = (const uint32_t*)&Bs[buf][0];
#pragma unroll
        for (int ks = 0; ks < 2; ks++) {
            const int kb = ks * 8;
            uint32_t af[4][4], bf[4][2];
#pragma unroll
            for (int mi = 0; mi < 4; mi++) {
                int base = (wm * 64 + mi * 16 + rr) * KST + kb + cc;
                af[mi][0] = As_[base];
                af[mi][1] = As_[base + 8 * KST];
                af[mi][2] = As_[base + 4];
                af[mi][3] = As_[base + 8 * KST + 4];
            }
#pragma unroll
            for (int ni = 0; ni < 4; ni++) {
                int base = (wn * 32 + ni * 8 + rr) * KST + kb + cc;
                bf[ni][0] = Bs_[base];
                bf[ni][1] = Bs_[base + 4];
            }
#pragma unroll
            for (int mi = 0; mi < 4; mi++)
#pragma unroll
                for (int ni = 0; ni < 4; ni++)
                    mma_tf32(acc[mi][ni], af[mi], bf[ni]);
        }
        __syncthreads();
    }

    // epilogue
#pragma unroll
    for (int mi = 0; mi < 4; mi++) {
#pragma unroll
        for (int ni = 0; ni < 4; ni++) {
            int gr = rowA0 + wm * 64 + mi * 16 + rr;
            int gc = rowB0 + wn * 32 + ni * 8 + 2 * cc;
            float b0v = 0.0f, b1v = 0.0f;
            if (bias) { b0v = bias[gc]; b1v = bias[gc + 1]; }
            float v00 = acc[mi][ni][0] * alpha + b0v;
            float v01 = acc[mi][ni][1] * alpha + b1v;
            float v10 = acc[mi][ni][2] * alpha + b0v;
            float v11 = acc[mi][ni][3] * alpha + b1v;
            if (roundC) {
                v00 = rtf(v00); v01 = rtf(v01); v10 = rtf(v10); v11 = rtf(v11);
            }
            if (!transC) {
                float2* o0 = (float2*)(Cb + (size_t)gr * Ncols + gc);
                *o0 = make_float2(v00, v01);
                float2* o1 = (float2*)(Cb + (size_t)(gr + 8) * Ncols + gc);
                *o1 = make_float2(v10, v11);
            } else {
                Cb[(size_t)gc * Mrows + gr]           = v00;
                Cb[(size_t)(gc + 1) * Mrows + gr]     = v01;
                Cb[(size_t)gc * Mrows + gr + 8]       = v10;
                Cb[(size_t)(gc + 1) * Mrows + gr + 8] = v11;
            }
        }
    }
}

// ---------------- kernel 3: softmax over last dim (256), in place, rounded probs ----------------
__global__ __launch_bounds__(256) void softmax256(float* __restrict__ S) {
    int row = blockIdx.x * 8 + (threadIdx.x >> 5);
    int lane = threadIdx.x & 31;
    float4* p = (float4*)(S + (size_t)row * MM);
    float4 v0 = p[lane];
    float4 v1 = p[lane + 32];

    float m = fmaxf(fmaxf(fmaxf(v0.x, v0.y), fmaxf(v0.z, v0.w)),
                    fmaxf(fmaxf(v1.x, v1.y), fmaxf(v1.z, v1.w)));
#pragma unroll
    for (int off = 16; off > 0; off >>= 1)
        m = fmaxf(m, __shfl_xor_sync(0xFFFFFFFFu, m, off));

    v0.x = __expf(v0.x - m); v0.y = __expf(v0.y - m);
    v0.z = __expf(v0.z - m); v0.w = __expf(v0.w - m);
    v1.x = __expf(v1.x - m); v1.y = __expf(v1.y - m);
    v1.z = __expf(v1.z - m); v1.w = __expf(v1.w - m);

    float s = v0.x + v0.y + v0.z + v0.w + v1.x + v1.y + v1.z + v1.w;
#pragma unroll
    for (int off = 16; off > 0; off >>= 1)
        s += __shfl_xor_sync(0xFFFFFFFFu, s, off);

    float inv = 1.0f / s;
    v0.x = rtf(v0.x * inv); v0.y = rtf(v0.y * inv);
    v0.z = rtf(v0.z * inv); v0.w = rtf(v0.w * inv);
    v1.x = rtf(v1.x * inv); v1.y = rtf(v1.y * inv);
    v1.z = rtf(v1.z * inv); v1.w = rtf(v1.w * inv);
    p[lane] = v0;
    p[lane + 32] = v1;
}

// ---------------- launch ----------------
extern "C" void kernel_launch(void* const* d_in, const int* in_sizes, int n_in,
                              void* d_out, int out_size) {
    static float *p_xr = nullptr, *p_W0, *p_W1, *p_W2, *p_W3,
                 *p_xm, *p_Q, *p_Km, *p_VmT, *p_S, *p_AO;
    if (!p_xr) {
        float* wbase;
        cudaGetSymbolAddress((void**)&p_xr,  g_xr);
        cudaGetSymbolAddress((void**)&wbase, g_Wr);
        p_W0 = wbase;
        p_W1 = wbase + (size_t)DD * DD;
        p_W2 = wbase + 2 * (size_t)DD * DD;
        p_W3 = wbase + 3 * (size_t)DD * DD;
        cudaGetSymbolAddress((void**)&p_xm,  g_xm);
        cudaGetSymbolAddress((void**)&p_Q,   g_Q);
        cudaGetSymbolAddress((void**)&p_Km,  g_Km);
        cudaGetSymbolAddress((void**)&p_VmT, g_VmT);
        cudaGetSymbolAddress((void**)&p_S,   g_S);
        cudaGetSymbolAddress((void**)&p_AO,  g_AO);
    }

    const float* x  = (const float*)d_in[0];
    const float* Wq = (const float*)d_in[1];
    const float* bq = (const float*)d_in[2];
    const float* Wk = (const float*)d_in[3];
    const float* bk = (const float*)d_in[4];
    const float* Wv = (const float*)d_in[5];
    const float* bv = (const float*)d_in[6];
    const float* Wo = (const float*)d_in[7];
    const float* bo = (const float*)d_in[8];
    float* out = (float*)d_out;

    const float scale = 1.0f / sqrtf((float)DD);
    dim3 blk(256);

    // Pre-round inputs to tf32-representable fp32 (removes cvt from GEMM inner loop)
    const int xN4 = BB * NN * (DD / 4);
    const int wN4 = DD * DD / 4;
    round_pass<<<(xN4 + 1023) / 1024, blk>>>((const float4*)x,  (float4*)p_xr, xN4);
    round_pass<<<(wN4 + 1023) / 1024, blk>>>((const float4*)Wq, (float4*)p_W0, wN4);
    round_pass<<<(wN4 + 1023) / 1024, blk>>>((const float4*)Wk, (float4*)p_W1, wN4);
    round_pass<<<(wN4 + 1023) / 1024, blk>>>((const float4*)Wv, (float4*)p_W2, wN4);
    round_pass<<<(wN4 + 1023) / 1024, blk>>>((const float4*)Wo, (float4*)p_W3, wN4);

    // 0. x_m = window mean of x_r (rounded)
    merge_mean<<<(BB * MM * (DD / 4)) / 256, blk>>>(p_xr, p_xm);

    // 1. Q = x @ Wq^T + bq      [32768, 1152]  (rounded)
    gemm_tf32<<<dim3((BB * NN) / BM, DD / BN, 1), blk>>>(
        p_xr, p_W0, bq, p_Q, BB * NN, DD, DD, 0, 0, 0, 1.0f, 0, 1);

    // 2. K_m = x_m @ Wk^T + bk  [8192, 1152]  (rounded)
    gemm_tf32<<<dim3((BB * MM) / BM, DD / BN, 1), blk>>>(
        p_xm, p_W1, bk, p_Km, BB * MM, DD, DD, 0, 0, 0, 1.0f, 0, 1);

    // 3. V_mT = (x_m @ Wv^T + bv)^T per batch  -> [32][1152][256]  (rounded)
    gemm_tf32<<<dim3(MM / BM, DD / BN, BB), blk>>>(
        p_xm, p_W2, bv, p_VmT, MM, DD, DD,
        (long long)MM * DD, 0, (long long)DD * MM, 1.0f, 1, 1);

    // 4. S = scale * Q @ K_m^T  (log(npt) bias dropped: softmax-invariant)
    gemm_tf32<<<dim3(NN / BM, MM / BN, BB), blk>>>(
        p_Q, p_Km, nullptr, p_S, NN, MM, DD,
        (long long)NN * DD, (long long)MM * DD, (long long)NN * MM, scale, 0, 0);

    // 5. softmax rows of S (writes rounded probs)
    softmax256<<<(BB * NN) / 8, blk>>>(p_S);

    // 6. AO = P @ V_m   (B operand = V_mT, K-major)  (rounded)
    gemm_tf32<<<dim3(NN / BM, DD / BN, BB), blk>>>(
        p_S, p_VmT, nullptr, p_AO, NN, DD, MM,
        (long long)NN * MM, (long long)DD * MM, (long long)NN * DD, 1.0f, 0, 1);

    // 7. out = AO @ Wo^T + bo   (full fp32 output)
    gemm_tf32<<<dim3((BB * NN) / BM, DD / BN, 1), blk>>>(
        p_AO, p_W3, bo, out, BB * NN, DD, DD, 0, 0, 0, 1.0f, 0, 0);
}

// round 5
// speedup vs baseline: 1.9558x; 1.5616x over previous
#include <cuda_runtime.h>
#include <cstdint>
#include <math.h>

// Problem constants
#define BB 32
#define NN 1024
#define DD 1152
#define RR 4
#define MM 256   // NN/RR

// GEMM tile config (Round-1 proven config)
#define BM 128
#define BN 128
#define BK 16
#define KST 20   // padded smem row stride (floats): 80B, 16B-aligned, conflict-free

// ---------------- scratch (device globals; no allocation allowed) ----------------
__device__ float g_xm  [(size_t)BB * MM * DD];   // merged x             [32,256,1152]
__device__ float g_xmT [(size_t)BB * DD * MM];   // merged x, transposed [32,1152,256]
__device__ float g_tWq [(size_t)DD * DD];        // Wq^T
__device__ float g_tWk [(size_t)DD * DD];        // Wk^T
__device__ float g_tWv [(size_t)DD * DD];        // Wv^T
__device__ float g_G   [(size_t)DD * DD];        // scale * Wq^T Wk
__device__ float g_H   [(size_t)DD * DD];        // Wo Wv
__device__ float g_T   [(size_t)BB * MM * DD];   // xm @ G^T             [32,256,1152]
__device__ float g_S   [(size_t)BB * NN * MM];   // logits/probs         [32,1024,256]
__device__ float g_U   [(size_t)BB * NN * DD];   // P @ xm               [32,1024,1152]
__device__ float g_c   [DD];                     // Wk^T bq
__device__ float g_b2  [DD];                     // Wo bv + bo
__device__ float g_beta[(size_t)BB * MM];        // scale * xm . c       [32,256]

// ---------------- helpers ----------------
__device__ __forceinline__ uint32_t f2tf32(float f) {
    uint32_t u;
    asm("cvt.rna.tf32.f32 %0, %1;" : "=r"(u) : "f"(f));
    return u;
}
__device__ __forceinline__ void cp_async16(uint32_t smem, const float* gmem) {
    asm volatile("cp.async.cg.shared.global [%0], [%1], 16;\n" :: "r"(smem), "l"(gmem));
}
__device__ __forceinline__ void cp_commit() {
    asm volatile("cp.async.commit_group;\n" ::: "memory");
}
__device__ __forceinline__ void mma_tf32(float c[4], const uint32_t a[4], const uint32_t b[2]) {
    asm volatile(
        "mma.sync.aligned.m16n8k8.row.col.f32.tf32.tf32.f32 "
        "{%0,%1,%2,%3}, {%4,%5,%6,%7}, {%8,%9}, {%0,%1,%2,%3};"
        : "+f"(c[0]), "+f"(c[1]), "+f"(c[2]), "+f"(c[3])
        : "r"(a[0]), "r"(a[1]), "r"(a[2]), "r"(a[3]), "r"(b[0]), "r"(b[1]));
}

// ---------------- kernel: window-mean merge  x[B,N,D] -> xm[B,M,D] ----------------
__global__ __launch_bounds__(256) void merge_mean(const float* __restrict__ x,
                                                  float* __restrict__ xm) {
    const int D4 = DD / 4;  // 288
    size_t idx = (size_t)blockIdx.x * blockDim.x + threadIdx.x;
    size_t tot = (size_t)BB * MM * D4;
    if (idx >= tot) return;
    int d4 = (int)(idx % D4);
    size_t orow = idx / D4;
    int b = (int)(orow >> 8);
    int m = (int)(orow & 255);
    const float4* base = (const float4*)x + ((size_t)b * NN + (size_t)m * RR) * D4 + d4;
    float4 a0 = base[0];
    float4 a1 = base[D4];
    float4 a2 = base[2 * D4];
    float4 a3 = base[3 * D4];
    float4 o;
    o.x = 0.25f * (a0.x + a1.x + a2.x + a3.x);
    o.y = 0.25f * (a0.y + a1.y + a2.y + a3.y);
    o.z = 0.25f * (a0.z + a1.z + a2.z + a3.z);
    o.w = 0.25f * (a0.w + a1.w + a2.w + a3.w);
    ((float4*)xm)[idx] = o;
}

// ---------------- kernel: tiled transpose  in[R,C] -> out[C,R], batched via z ----------------
__global__ void transpose_k(const float* __restrict__ in, float* __restrict__ out,
                            int R, int C, long long sIn, long long sOut) {
    __shared__ float t[32][33];
    const float* ib = in + (size_t)blockIdx.z * sIn;
    float* ob = out + (size_t)blockIdx.z * sOut;
    int bx = blockIdx.x * 32, by = blockIdx.y * 32;
    int x = bx + threadIdx.x;
    {
        int y = by + threadIdx.y;
#pragma unroll
        for (int dy = 0; dy < 32; dy += 8)
            if (y + dy < R && x < C) t[threadIdx.y + dy][threadIdx.x] = ib[(size_t)(y + dy) * C + x];
    }
    __syncthreads();
    {
        int x2 = by + threadIdx.x;
        int y2 = bx + threadIdx.y;
#pragma unroll
        for (int dy = 0; dy < 32; dy += 8)
            if (y2 + dy < C && x2 < R) ob[(size_t)(y2 + dy) * R + x2] = t[threadIdx.x][threadIdx.y + dy];
    }
}

// ---------------- kernel: column matvec  c[j] = sum_d W[d][j] * b[d] ----------------
__global__ __launch_bounds__(256) void colvec(const float* __restrict__ W,
                                              const float* __restrict__ b,
                                              float* __restrict__ c) {
    int j = blockIdx.x * 256 + threadIdx.x;
    if (j >= DD) return;
    float s = 0.f;
    for (int d = 0; d < DD; d++) s += W[(size_t)d * DD + j] * b[d];
    c[j] = s;
}

// ---------------- kernel: row matvec  out[o] = sum_d W[o][d]*b[d] + b0[o] ----------------
__global__ __launch_bounds__(256) void rowvec(const float* __restrict__ W,
                                              const float* __restrict__ b,
                                              const float* __restrict__ b0,
                                              float* __restrict__ out) {
    int row = blockIdx.x * 8 + (threadIdx.x >> 5);
    int lane = threadIdx.x & 31;
    if (row >= DD) return;
    float s = 0.f;
    const float* wr = W + (size_t)row * DD;
    for (int d = lane; d < DD; d += 32) s += wr[d] * b[d];
#pragma unroll
    for (int o = 16; o; o >>= 1) s += __shfl_xor_sync(0xFFFFFFFFu, s, o);
    if (!lane) out[row] = s + b0[row];
}

// ---------------- kernel: beta[row] = scale * dot(xm[row,:], c)  (row over B*M) ----------------
__global__ __launch_bounds__(256) void betak(const float* __restrict__ xm,
                                             const float* __restrict__ c,
                                             float* __restrict__ beta, float scale) {
    int row = blockIdx.x * 8 + (threadIdx.x >> 5);
    int lane = threadIdx.x & 31;
    float s = 0.f;
    const float* p = xm + (size_t)row * DD;
    for (int d = lane; d < DD; d += 32) s += p[d] * c[d];
#pragma unroll
    for (int o = 16; o; o >>= 1) s += __shfl_xor_sync(0xFFFFFFFFu, s, o);
    if (!lane) beta[row] = s * scale;
}

// ---------------- batched tf32 GEMM (Round-1 proven) + per-batch bias stride ----------------
// C[b][i][j] = alpha * sum_k A[b][i][k] * Bm[b][j][k]  (+ bias[b*sBias + j] if bias)
__global__ __launch_bounds__(256) void gemm_tf32(
    const float* __restrict__ A, const float* __restrict__ Bm,
    const float* __restrict__ bias, float* __restrict__ C,
    int Ncols, int K,
    long long sA, long long sB, long long sC, long long sBias,
    float alpha)
{
    __shared__ float As[2][BM * KST];
    __shared__ float Bs[2][BN * KST];

    const int bz = blockIdx.z;
    const float* Ab = A + (size_t)bz * sA;
    const float* Bb = Bm + (size_t)bz * sB;
    float* Cb = C + (size_t)bz * sC;
    const float* bp = bias ? bias + (size_t)bz * sBias : nullptr;

    const int tid = threadIdx.x;
    const int warp = tid >> 5, lane = tid & 31;
    const int wm = warp & 1;
    const int wn = warp >> 1;
    const int rr = lane >> 2;
    const int cc = lane & 3;

    const int rowA0 = blockIdx.x * BM;
    const int rowB0 = blockIdx.y * BN;

    float acc[4][4][4];
#pragma unroll
    for (int i = 0; i < 4; i++)
#pragma unroll
        for (int j = 0; j < 4; j++)
#pragma unroll
            for (int k = 0; k < 4; k++) acc[i][j][k] = 0.0f;

    const int KT = K / BK;

    auto load_tile = [&](int buf, int kt) {
#pragma unroll
        for (int i = 0; i < 2; i++) {
            int c = tid + i * 256;
            int r = c >> 2;
            int kv = (c & 3) * 4;
            const float* gA = Ab + (size_t)(rowA0 + r) * K + kt * BK + kv;
            uint32_t sa = (uint32_t)__cvta_generic_to_shared(&As[buf][r * KST + kv]);
            cp_async16(sa, gA);
            const float* gB = Bb + (size_t)(rowB0 + r) * K + kt * BK + kv;
            uint32_t sb = (uint32_t)__cvta_generic_to_shared(&Bs[buf][r * KST + kv]);
            cp_async16(sb, gB);
        }
        cp_commit();
    };

    load_tile(0, 0);

    for (int kt = 0; kt < KT; kt++) {
        const int buf = kt & 1;
        if (kt + 1 < KT) {
            load_tile(buf ^ 1, kt + 1);
            asm volatile("cp.async.wait_group 1;\n" ::: "memory");
        } else {
            asm volatile("cp.async.wait_group 0;\n" ::: "memory");
        }
        __syncthreads();

        const float* As_ = &As[buf][0];
        const float* Bs_ = &Bs[buf][0];
#pragma unroll
        for (int ks = 0; ks < 2; ks++) {
            const int kb = ks * 8;
            uint32_t af[4][4], bf[4][2];
#pragma unroll
            for (int mi = 0; mi < 4; mi++) {
                int base = (wm * 64 + mi * 16 + rr) * KST + kb + cc;
                af[mi][0] = f2tf32(As_[base]);
                af[mi][1] = f2tf32(As_[base + 8 * KST]);
                af[mi][2] = f2tf32(As_[base + 4]);
                af[mi][3] = f2tf32(As_[base + 8 * KST + 4]);
            }
#pragma unroll
            for (int ni = 0; ni < 4; ni++) {
                int base = (wn * 32 + ni * 8 + rr) * KST + kb + cc;
                bf[ni][0] = f2tf32(Bs_[base]);
                bf[ni][1] = f2tf32(Bs_[base + 4]);
            }
#pragma unroll
            for (int mi = 0; mi < 4; mi++)
#pragma unroll
                for (int ni = 0; ni < 4; ni++)
                    mma_tf32(acc[mi][ni], af[mi], bf[ni]);
        }
        __syncthreads();
    }

#pragma unroll
    for (int mi = 0; mi < 4; mi++) {
#pragma unroll
        for (int ni = 0; ni < 4; ni++) {
            int gr = rowA0 + wm * 64 + mi * 16 + rr;
            int gc = rowB0 + wn * 32 + ni * 8 + 2 * cc;
            float b0v = 0.0f, b1v = 0.0f;
            if (bp) { b0v = bp[gc]; b1v = bp[gc + 1]; }
            float v00 = acc[mi][ni][0] * alpha + b0v;
            float v01 = acc[mi][ni][1] * alpha + b1v;
            float v10 = acc[mi][ni][2] * alpha + b0v;
            float v11 = acc[mi][ni][3] * alpha + b1v;
            float2* o0 = (float2*)(Cb + (size_t)gr * Ncols + gc);
            *o0 = make_float2(v00, v01);
            float2* o1 = (float2*)(Cb + (size_t)(gr + 8) * Ncols + gc);
            *o1 = make_float2(v10, v11);
        }
    }
}

// ---------------- softmax over last dim (256), in place ----------------
__global__ __launch_bounds__(256) void softmax256(float* __restrict__ S) {
    int row = blockIdx.x * 8 + (threadIdx.x >> 5);
    int lane = threadIdx.x & 31;
    float4* p = (float4*)(S + (size_t)row * MM);
    float4 v0 = p[lane];
    float4 v1 = p[lane + 32];

    float m = fmaxf(fmaxf(fmaxf(v0.x, v0.y), fmaxf(v0.z, v0.w)),
                    fmaxf(fmaxf(v1.x, v1.y), fmaxf(v1.z, v1.w)));
#pragma unroll
    for (int off = 16; off > 0; off >>= 1)
        m = fmaxf(m, __shfl_xor_sync(0xFFFFFFFFu, m, off));

    v0.x = __expf(v0.x - m); v0.y = __expf(v0.y - m);
    v0.z = __expf(v0.z - m); v0.w = __expf(v0.w - m);
    v1.x = __expf(v1.x - m); v1.y = __expf(v1.y - m);
    v1.z = __expf(v1.z - m); v1.w = __expf(v1.w - m);

    float s = v0.x + v0.y + v0.z + v0.w + v1.x + v1.y + v1.z + v1.w;
#pragma unroll
    for (int off = 16; off > 0; off >>= 1)
        s += __shfl_xor_sync(0xFFFFFFFFu, s, off);

    float inv = 1.0f / s;
    v0.x *= inv; v0.y *= inv; v0.z *= inv; v0.w *= inv;
    v1.x *= inv; v1.y *= inv; v1.z *= inv; v1.w *= inv;
    p[lane] = v0;
    p[lane + 32] = v1;
}

// ---------------- launch ----------------
extern "C" void kernel_launch(void* const* d_in, const int* in_sizes, int n_in,
                              void* d_out, int out_size) {
    static float *p_xm = nullptr, *p_xmT, *p_tWq, *p_tWk, *p_tWv,
                 *p_G, *p_H, *p_T, *p_S, *p_U, *p_c, *p_b2, *p_beta;
    if (!p_xm) {
        cudaGetSymbolAddress((void**)&p_xm,   g_xm);
        cudaGetSymbolAddress((void**)&p_xmT,  g_xmT);
        cudaGetSymbolAddress((void**)&p_tWq,  g_tWq);
        cudaGetSymbolAddress((void**)&p_tWk,  g_tWk);
        cudaGetSymbolAddress((void**)&p_tWv,  g_tWv);
        cudaGetSymbolAddress((void**)&p_G,    g_G);
        cudaGetSymbolAddress((void**)&p_H,    g_H);
        cudaGetSymbolAddress((void**)&p_T,    g_T);
        cudaGetSymbolAddress((void**)&p_S,    g_S);
        cudaGetSymbolAddress((void**)&p_U,    g_U);
        cudaGetSymbolAddress((void**)&p_c,    g_c);
        cudaGetSymbolAddress((void**)&p_b2,   g_b2);
        cudaGetSymbolAddress((void**)&p_beta, g_beta);
    }

    const float* x  = (const float*)d_in[0];
    const float* Wq = (const float*)d_in[1];
    const float* bq = (const float*)d_in[2];
    const float* Wk = (const float*)d_in[3];
    const float* bk = (const float*)d_in[4];   // drops out of softmax (row-constant)
    const float* Wv = (const float*)d_in[5];
    const float* bv = (const float*)d_in[6];
    const float* Wo = (const float*)d_in[7];
    const float* bo = (const float*)d_in[8];
    float* out = (float*)d_out;
    (void)bk;

    const float scale = 1.0f / sqrtf((float)DD);
    dim3 blk(256);
    dim3 tblk(32, 8);

    // ---- small precomputations ----
    // transposes of weights
    transpose_k<<<dim3(36, 36, 1), tblk>>>(Wq, p_tWq, DD, DD, 0, 0);
    transpose_k<<<dim3(36, 36, 1), tblk>>>(Wk, p_tWk, DD, DD, 0, 0);
    transpose_k<<<dim3(36, 36, 1), tblk>>>(Wv, p_tWv, DD, DD, 0, 0);
    // c = Wk^T bq ; b2 = Wo bv + bo
    colvec<<<(DD + 255) / 256, blk>>>(Wk, bq, p_c);
    rowvec<<<(DD + 7) / 8, blk>>>(Wo, bv, bo, p_b2);
    // G = scale * Wq^T Wk  : G[i][j] = scale * sum_k tWq[i,k] tWk[j,k]
    gemm_tf32<<<dim3(9, 9, 1), blk>>>(p_tWq, p_tWk, nullptr, p_G, DD, DD, 0, 0, 0, 0, scale);
    // H = Wo Wv : H[i][j] = sum_k Wo[i,k] tWv[j,k]
    gemm_tf32<<<dim3(9, 9, 1), blk>>>(Wo, p_tWv, nullptr, p_H, DD, DD, 0, 0, 0, 0, 1.0f);

    // ---- data path ----
    // xm = window mean of x ; xmT per batch
    merge_mean<<<(BB * MM * (DD / 4)) / 256, blk>>>(x, p_xm);
    transpose_k<<<dim3(36, 8, BB), tblk>>>(p_xm, p_xmT, MM, DD,
                                           (long long)MM * DD, (long long)DD * MM);
    // beta[b,m] = scale * xm[b,m,:] . c
    betak<<<(BB * MM) / 8, blk>>>(p_xm, p_c, p_beta, scale);

    // T = xm_flat @ G^T  : [8192, 1152]
    gemm_tf32<<<dim3(64, 9, 1), blk>>>(p_xm, p_G, nullptr, p_T, DD, DD, 0, 0, 0, 0, 1.0f);

    // S[b] = x[b] @ T[b]^T + beta[b,:]   [1024, 256] per batch
    gemm_tf32<<<dim3(8, 2, BB), blk>>>(
        x, p_T, p_beta, p_S, MM, DD,
        (long long)NN * DD, (long long)MM * DD, (long long)NN * MM, MM, 1.0f);

    // softmax rows of S
    softmax256<<<(BB * NN) / 8, blk>>>(p_S);

    // U[b] = P[b] @ xm[b]  (B operand = xmT, K-major over m)   [1024, 1152] per batch
    gemm_tf32<<<dim3(8, 9, BB), blk>>>(
        p_S, p_xmT, nullptr, p_U, DD, MM,
        (long long)NN * MM, (long long)DD * MM, (long long)NN * DD, 0, 1.0f);

    // out = U_flat @ H^T + b2   [32768, 1152]
    gemm_tf32<<<dim3(256, 9, 1), blk>>>(p_U, p_H, p_b2, out, DD, DD, 0, 0, 0, 0, 1.0f);
}

// round 6
// speedup vs baseline: 3.2436x; 1.6585x over previous
#include <cuda_runtime.h>
#include <cstdint>
#include <math.h>

// Problem constants
#define BB 32
#define NN 1024
#define DD 1152
#define RR 4
#define MM 256   // NN/RR

// GEMM tile config (proven)
#define BM 128
#define BN 128
#define BK 16
#define KST 20

// ---------------- scratch ----------------
__device__ float g_xm  [(size_t)BB * MM * DD];   // merged x            [32,256,1152]
__device__ float g_PA  [2 * (size_t)DD * DD];    // pack A: [Wq^T ; Wo]
__device__ float g_PB  [2 * (size_t)DD * DD];    // pack B: [Wk^T ; Wv^T]
__device__ float g_GH  [2 * (size_t)DD * DD];    // [G0 = Wq^T Wk ; H = Wo Wv]
__device__ float g_T   [(size_t)BB * MM * DD];   // xm @ G0^T           [32,256,1152]
__device__ float g_S   [(size_t)BB * NN * MM];   // logits/probs        [32,1024,256]
__device__ float g_YT  [(size_t)BB * DD * MM];   // (xm @ H^T)^T        [32,1152,256]
__device__ float g_c   [DD];                     // Wk^T bq
__device__ float g_b2  [DD];                     // Wo bv + bo
__device__ float g_beta[(size_t)BB * MM];        // scale * xm . c

// ---------------- helpers ----------------
__device__ __forceinline__ uint32_t f2tf32(float f) {
    uint32_t u;
    asm("cvt.rna.tf32.f32 %0, %1;" : "=r"(u) : "f"(f));
    return u;
}
__device__ __forceinline__ void cp_async16(uint32_t smem, const float* gmem) {
    asm volatile("cp.async.cg.shared.global [%0], [%1], 16;\n" :: "r"(smem), "l"(gmem));
}
__device__ __forceinline__ void cp_commit() {
    asm volatile("cp.async.commit_group;\n" ::: "memory");
}
__device__ __forceinline__ void mma_tf32(float c[4], const uint32_t a[4], const uint32_t b[2]) {
    asm volatile(
        "mma.sync.aligned.m16n8k8.row.col.f32.tf32.tf32.f32 "
        "{%0,%1,%2,%3}, {%4,%5,%6,%7}, {%8,%9}, {%0,%1,%2,%3};"
        : "+f"(c[0]), "+f"(c[1]), "+f"(c[2]), "+f"(c[3])
        : "r"(a[0]), "r"(a[1]), "r"(a[2]), "r"(a[3]), "r"(b[0]), "r"(b[1]));
}

// ---------------- window-mean merge ----------------
__global__ __launch_bounds__(256) void merge_mean(const float* __restrict__ x,
                                                  float* __restrict__ xm) {
    const int D4 = DD / 4;
    size_t idx = (size_t)blockIdx.x * blockDim.x + threadIdx.x;
    size_t tot = (size_t)BB * MM * D4;
    if (idx >= tot) return;
    int d4 = (int)(idx % D4);
    size_t orow = idx / D4;
    int b = (int)(orow >> 8);
    int m = (int)(orow & 255);
    const float4* base = (const float4*)x + ((size_t)b * NN + (size_t)m * RR) * D4 + d4;
    float4 a0 = base[0];
    float4 a1 = base[D4];
    float4 a2 = base[2 * D4];
    float4 a3 = base[3 * D4];
    float4 o;
    o.x = 0.25f * (a0.x + a1.x + a2.x + a3.x);
    o.y = 0.25f * (a0.y + a1.y + a2.y + a3.y);
    o.z = 0.25f * (a0.z + a1.z + a2.z + a3.z);
    o.w = 0.25f * (a0.w + a1.w + a2.w + a3.w);
    ((float4*)xm)[idx] = o;
}

// ---------------- tiled transpose (square DD x DD here) ----------------
__global__ void transpose_k(const float* __restrict__ in, float* __restrict__ out,
                            int R, int C) {
    __shared__ float t[32][33];
    int bx = blockIdx.x * 32, by = blockIdx.y * 32;
    int x = bx + threadIdx.x;
    {
        int y = by + threadIdx.y;
#pragma unroll
        for (int dy = 0; dy < 32; dy += 8)
            if (y + dy < R && x < C) t[threadIdx.y + dy][threadIdx.x] = in[(size_t)(y + dy) * C + x];
    }
    __syncthreads();
    {
        int x2 = by + threadIdx.x;
        int y2 = bx + threadIdx.y;
#pragma unroll
        for (int dy = 0; dy < 32; dy += 8)
            if (y2 + dy < C && x2 < R) out[(size_t)(y2 + dy) * R + x2] = t[threadIdx.x][threadIdx.y + dy];
    }
}

// ---------------- float4 copy ----------------
__global__ __launch_bounds__(256) void copy4(const float4* __restrict__ in,
                                             float4* __restrict__ out, int n4) {
    int i = blockIdx.x * 256 + threadIdx.x;
    if (i < n4) out[i] = in[i];
}

// ---------------- row matvec: out[r] = sum_d W[r][d]*b[d] (+ b0[r]) ----------------
__global__ __launch_bounds__(256) void rowvec(const float* __restrict__ W,
                                              const float* __restrict__ b,
                                              const float* __restrict__ b0,
                                              float* __restrict__ out) {
    int row = blockIdx.x * 8 + (threadIdx.x >> 5);
    int lane = threadIdx.x & 31;
    if (row >= DD) return;
    float s = 0.f;
    const float* wr = W + (size_t)row * DD;
    for (int d = lane; d < DD; d += 32) s += wr[d] * b[d];
#pragma unroll
    for (int o = 16; o; o >>= 1) s += __shfl_xor_sync(0xFFFFFFFFu, s, o);
    if (!lane) out[row] = b0 ? (s + b0[row]) : s;
}

// ---------------- beta[row] = scale * dot(xm[row,:], c) ----------------
__global__ __launch_bounds__(256) void betak(const float* __restrict__ xm,
                                             const float* __restrict__ c,
                                             float* __restrict__ beta, float scale) {
    int row = blockIdx.x * 8 + (threadIdx.x >> 5);
    int lane = threadIdx.x & 31;
    float s = 0.f;
    const float* p = xm + (size_t)row * DD;
    for (int d = lane; d < DD; d += 32) s += p[d] * c[d];
#pragma unroll
    for (int o = 16; o; o >>= 1) s += __shfl_xor_sync(0xFFFFFFFFu, s, o);
    if (!lane) beta[row] = s * scale;
}

// ---------------- batched tf32 GEMM ----------------
// C[b][i][j] = alpha * sum_k A[b][i][k] * Bm[b][j][k]  (+ bias[b*sBias + j])
__global__ __launch_bounds__(256) void gemm_tf32(
    const float* __restrict__ A, const float* __restrict__ Bm,
    const float* __restrict__ bias, float* __restrict__ C,
    int Ncols, int K,
    long long sA, long long sB, long long sC, long long sBias,
    float alpha)
{
    __shared__ float As[2][BM * KST];
    __shared__ float Bs[2][BN * KST];

    const int bz = blockIdx.z;
    const float* Ab = A + (size_t)bz * sA;
    const float* Bb = Bm + (size_t)bz * sB;
    float* Cb = C + (size_t)bz * sC;
    const float* bp = bias ? bias + (size_t)bz * sBias : nullptr;

    const int tid = threadIdx.x;
    const int warp = tid >> 5, lane = tid & 31;
    const int wm = warp & 1;
    const int wn = warp >> 1;
    const int rr = lane >> 2;
    const int cc = lane & 3;

    const int rowA0 = blockIdx.x * BM;
    const int rowB0 = blockIdx.y * BN;

    float acc[4][4][4];
#pragma unroll
    for (int i = 0; i < 4; i++)
#pragma unroll
        for (int j = 0; j < 4; j++)
#pragma unroll
            for (int k = 0; k < 4; k++) acc[i][j][k] = 0.0f;

    const int KT = K / BK;

    auto load_tile = [&](int buf, int kt) {
#pragma unroll
        for (int i = 0; i < 2; i++) {
            int c = tid + i * 256;
            int r = c >> 2;
            int kv = (c & 3) * 4;
            const float* gA = Ab + (size_t)(rowA0 + r) * K + kt * BK + kv;
            uint32_t sa = (uint32_t)__cvta_generic_to_shared(&As[buf][r * KST + kv]);
            cp_async16(sa, gA);
            const float* gB = Bb + (size_t)(rowB0 + r) * K + kt * BK + kv;
            uint32_t sb = (uint32_t)__cvta_generic_to_shared(&Bs[buf][r * KST + kv]);
            cp_async16(sb, gB);
        }
        cp_commit();
    };

    load_tile(0, 0);

    for (int kt = 0; kt < KT; kt++) {
        const int buf = kt & 1;
        if (kt + 1 < KT) {
            load_tile(buf ^ 1, kt + 1);
            asm volatile("cp.async.wait_group 1;\n" ::: "memory");
        } else {
            asm volatile("cp.async.wait_group 0;\n" ::: "memory");
        }
        __syncthreads();

        const float* As_ = &As[buf][0];
        const float* Bs_ = &Bs[buf][0];
#pragma unroll
        for (int ks = 0; ks < 2; ks++) {
            const int kb = ks * 8;
            uint32_t af[4][4], bf[4][2];
#pragma unroll
            for (int mi = 0; mi < 4; mi++) {
                int base = (wm * 64 + mi * 16 + rr) * KST + kb + cc;
                af[mi][0] = f2tf32(As_[base]);
                af[mi][1] = f2tf32(As_[base + 8 * KST]);
                af[mi][2] = f2tf32(As_[base + 4]);
                af[mi][3] = f2tf32(As_[base + 8 * KST + 4]);
            }
#pragma unroll
            for (int ni = 0; ni < 4; ni++) {
                int base = (wn * 32 + ni * 8 + rr) * KST + kb + cc;
                bf[ni][0] = f2tf32(Bs_[base]);
                bf[ni][1] = f2tf32(Bs_[base + 4]);
            }
#pragma unroll
            for (int mi = 0; mi < 4; mi++)
#pragma unroll
                for (int ni = 0; ni < 4; ni++)
                    mma_tf32(acc[mi][ni], af[mi], bf[ni]);
        }
        __syncthreads();
    }

#pragma unroll
    for (int mi = 0; mi < 4; mi++) {
#pragma unroll
        for (int ni = 0; ni < 4; ni++) {
            int gr = rowA0 + wm * 64 + mi * 16 + rr;
            int gc = rowB0 + wn * 32 + ni * 8 + 2 * cc;
            float b0v = 0.0f, b1v = 0.0f;
            if (bp) { b0v = bp[gc]; b1v = bp[gc + 1]; }
            float v00 = acc[mi][ni][0] * alpha + b0v;
            float v01 = acc[mi][ni][1] * alpha + b1v;
            float v10 = acc[mi][ni][2] * alpha + b0v;
            float v11 = acc[mi][ni][3] * alpha + b1v;
            float2* o0 = (float2*)(Cb + (size_t)gr * Ncols + gc);
            *o0 = make_float2(v00, v01);
            float2* o1 = (float2*)(Cb + (size_t)(gr + 8) * Ncols + gc);
            *o1 = make_float2(v10, v11);
        }
    }
}

// ---------------- softmax over last dim (256), in place ----------------
__global__ __launch_bounds__(256) void softmax256(float* __restrict__ S) {
    int row = blockIdx.x * 8 + (threadIdx.x >> 5);
    int lane = threadIdx.x & 31;
    float4* p = (float4*)(S + (size_t)row * MM);
    float4 v0 = p[lane];
    float4 v1 = p[lane + 32];

    float m = fmaxf(fmaxf(fmaxf(v0.x, v0.y), fmaxf(v0.z, v0.w)),
                    fmaxf(fmaxf(v1.x, v1.y), fmaxf(v1.z, v1.w)));
#pragma unroll
    for (int off = 16; off > 0; off >>= 1)
        m = fmaxf(m, __shfl_xor_sync(0xFFFFFFFFu, m, off));

    v0.x = __expf(v0.x - m); v0.y = __expf(v0.y - m);
    v0.z = __expf(v0.z - m); v0.w = __expf(v0.w - m);
    v1.x = __expf(v1.x - m); v1.y = __expf(v1.y - m);
    v1.z = __expf(v1.z - m); v1.w = __expf(v1.w - m);

    float s = v0.x + v0.y + v0.z + v0.w + v1.x + v1.y + v1.z + v1.w;
#pragma unroll
    for (int off = 16; off > 0; off >>= 1)
        s += __shfl_xor_sync(0xFFFFFFFFu, s, off);

    float inv = 1.0f / s;
    v0.x *= inv; v0.y *= inv; v0.z *= inv; v0.w *= inv;
    v1.x *= inv; v1.y *= inv; v1.z *= inv; v1.w *= inv;
    p[lane] = v0;
    p[lane + 32] = v1;
}

// ---------------- launch ----------------
extern "C" void kernel_launch(void* const* d_in, const int* in_sizes, int n_in,
                              void* d_out, int out_size) {
    static float *p_xm = nullptr, *p_PA, *p_PB, *p_GH, *p_T, *p_S, *p_YT,
                 *p_c, *p_b2, *p_beta;
    if (!p_xm) {
        cudaGetSymbolAddress((void**)&p_xm,   g_xm);
        cudaGetSymbolAddress((void**)&p_PA,   g_PA);
        cudaGetSymbolAddress((void**)&p_PB,   g_PB);
        cudaGetSymbolAddress((void**)&p_GH,   g_GH);
        cudaGetSymbolAddress((void**)&p_T,    g_T);
        cudaGetSymbolAddress((void**)&p_S,    g_S);
        cudaGetSymbolAddress((void**)&p_YT,   g_YT);
        cudaGetSymbolAddress((void**)&p_c,    g_c);
        cudaGetSymbolAddress((void**)&p_b2,   g_b2);
        cudaGetSymbolAddress((void**)&p_beta, g_beta);
    }

    const float* x  = (const float*)d_in[0];
    const float* Wq = (const float*)d_in[1];
    const float* bq = (const float*)d_in[2];
    const float* Wk = (const float*)d_in[3];
    const float* bk = (const float*)d_in[4];   // row-constant in logits: drops under softmax
    const float* Wv = (const float*)d_in[5];
    const float* bv = (const float*)d_in[6];
    const float* Wo = (const float*)d_in[7];
    const float* bo = (const float*)d_in[8];
    float* out = (float*)d_out;
    (void)bk;

    const float scale = 1.0f / sqrtf((float)DD);
    const size_t W2 = (size_t)DD * DD;
    dim3 blk(256);
    dim3 tblk(32, 8);

    // ---- weight prep (packed) ----
    transpose_k<<<dim3(36, 36), tblk>>>(Wq, p_PA, DD, DD);          // PA0 = Wq^T
    copy4<<<(int)(W2 / 4 + 255) / 256, blk>>>((const float4*)Wo,
                                              (float4*)(p_PA + W2), (int)(W2 / 4)); // PA1 = Wo
    transpose_k<<<dim3(36, 36), tblk>>>(Wk, p_PB, DD, DD);          // PB0 = Wk^T
    transpose_k<<<dim3(36, 36), tblk>>>(Wv, p_PB + W2, DD, DD);     // PB1 = Wv^T

    // c = Wk^T bq  (rows of PB0, coalesced);  b2 = Wo bv + bo
    rowvec<<<(DD + 7) / 8, blk>>>(p_PB, bq, nullptr, p_c);
    rowvec<<<(DD + 7) / 8, blk>>>(Wo, bv, bo, p_b2);

    // [G0 ; H] = [Wq^T@Wk ; Wo@Wv] in one z=2 GEMM (A@B^T with B pre-transposed)
    gemm_tf32<<<dim3(9, 9, 2), blk>>>(p_PA, p_PB, nullptr, p_GH, DD, DD,
                                      (long long)W2, (long long)W2, (long long)W2, 0, 1.0f);

    // ---- data path ----
    merge_mean<<<(BB * MM * (DD / 4)) / 256, blk>>>(x, p_xm);
    betak<<<(BB * MM) / 8, blk>>>(p_xm, p_c, p_beta, scale);

    // T = xm_flat @ G0^T   [8192, 1152]
    gemm_tf32<<<dim3(64, 9, 1), blk>>>(p_xm, p_GH, nullptr, p_T, DD, DD, 0, 0, 0, 0, 1.0f);

    // S[b] = scale * x[b] @ T[b]^T + beta[b,:]   [1024, 256]
    gemm_tf32<<<dim3(8, 2, BB), blk>>>(
        x, p_T, p_beta, p_S, MM, DD,
        (long long)NN * DD, (long long)MM * DD, (long long)NN * MM, MM, scale);

    // softmax rows of S -> P
    softmax256<<<(BB * NN) / 8, blk>>>(p_S);

    // YT[b] = H @ xm[b]^T   [1152, 256]  (A=H shared, B=xm batched; direct transposed output)
    gemm_tf32<<<dim3(9, 2, BB), blk>>>(
        p_GH + W2, p_xm, nullptr, p_YT, MM, DD,
        0, (long long)MM * DD, (long long)DD * MM, 0, 1.0f);

    // out[b] = P[b] @ YT[b]^T + b2   [1024, 1152]  (K = 256)
    gemm_tf32<<<dim3(8, 9, BB), blk>>>(
        p_S, p_YT, p_b2, out, DD, MM,
        (long long)NN * MM, (long long)DD * MM, (long long)NN * DD, 0, 1.0f);
}